// round 3
// baseline (speedup 1.0000x reference)
#include <cuda_runtime.h>
#include <cuda_bf16.h>

// ExponentialSmoothingLayer: s_0 = x_0; s_t = a*x_t + (1-a)*s_{t-1}, a = sigmoid(alpha[d])
// x: (B=16, T=4096, D=512) fp32, alpha: (512,) fp32, out: same shape as x.
//
// Single-pass decoupled-lookback linear scan:
//   - tile = (b, 32 timesteps, all 512 d); block = 512 threads (thread <-> d)
//   - local scan in registers; aggregate (last, q^32) published with release flag
//   - lookback combines predecessor aggregates/inclusives (linear-recurrence algebra)
//   - total DRAM traffic ~= read x once + write out once (+16MB scratch)

#define B_  16
#define T_  4096
#define D_  512
#define L_  32                   // timesteps per tile
#define NTB (T_ / L_)            // 128 tiles per batch row
#define NTILES (B_ * NTB)        // 2048 tiles total
#define TPB 512

// -------- scratch (static __device__ arrays; no runtime allocation) --------
__device__ float        g_agg [NTILES * D_];   // tile-local last value (zero-init state)
__device__ float        g_incl[NTILES * D_];   // tile inclusive (true s at tile end)
__device__ int          g_status[NTILES];      // 0 = invalid, 1 = aggregate, 2 = inclusive
__device__ unsigned int g_ticket;

// -------- acquire/release helpers --------
__device__ __forceinline__ int ld_acquire(const int* p) {
    int v;
    asm volatile("ld.acquire.gpu.s32 %0, [%1];" : "=r"(v) : "l"(p) : "memory");
    return v;
}
__device__ __forceinline__ void st_release(int* p, int v) {
    asm volatile("st.release.gpu.s32 [%0], %1;" :: "l"(p), "r"(v) : "memory");
}

// -------- per-launch flag reset (graph replays poison nothing; we must clear) --------
__global__ void es_clear_kernel() {
    int i = blockIdx.x * blockDim.x + threadIdx.x;
    if (i < NTILES) g_status[i] = 0;
    if (i == 0)     g_ticket = 0u;
}

__global__ void __launch_bounds__(TPB, 2)
es_scan_kernel(const float* __restrict__ x,
               const float* __restrict__ alpha,
               float* __restrict__ out) {
    __shared__ unsigned s_ticket;
    if (threadIdx.x == 0) s_ticket = atomicAdd(&g_ticket, 1u);
    __syncthreads();

    const unsigned ticket = s_ticket;       // flat tile id, execution-start ordered
    const int b  = (int)(ticket % B_);      // interleave batches across consecutive tickets
    const int tb = (int)(ticket / B_);      // tile index along T within batch b
    const int d  = threadIdx.x;

    // per-channel smoothing coefficients
    const float av = alpha[d];
    const float a  = 1.0f / (1.0f + __expf(-av));
    const float q  = 1.0f - a;
    float Q = q;                             // Q = q^L  (L = 32 -> 5 squarings)
    #pragma unroll
    for (int i = 0; i < 5; ++i) Q *= Q;

    const size_t base = ((size_t)b * T_ + (size_t)tb * L_) * (size_t)D_ + (size_t)d;
    const float* xp = x + base;

    // front-batched loads: 32 independent LDGs per thread (MLP)
    float v[L_];
    #pragma unroll
    for (int i = 0; i < L_; ++i) v[i] = xp[(size_t)i * D_];

    const float x0 = v[0];                   // needed for tile 0's init state

    // tile-local scan with zero incoming state: l_i = a*x_i + q*l_{i-1}
    float s = 0.0f;
    #pragma unroll
    for (int i = 0; i < L_; ++i) {
        s = fmaf(q, s, a * v[i]);
        v[i] = s;
    }
    const float last = s;

    // ---- resolve incoming state S_in = inclusive of predecessor tile ----
    float carry;
    if (tb == 0) {
        // s_0 = x_0  <=>  S_in = x_0  (a*x0 + q*x0 = x0)
        carry = x0;
    } else {
        // publish aggregate FIRST (guarantees forward progress for successors)
        g_agg[(size_t)ticket * D_ + d] = last;
        __threadfence();
        __syncthreads();
        if (threadIdx.x == 0) st_release(&g_status[ticket], 1);

        // decoupled lookback: carry = last_{j} + Q*last_{j-1} + ... + Q^k * incl_{j-k}
        carry = 0.0f;
        float coef = 1.0f;
        int j = (int)ticket - B_;            // same-b predecessor
        for (;;) {
            int st = ld_acquire(&g_status[j]);
            while (st == 0) {
                __nanosleep(40);
                st = ld_acquire(&g_status[j]);
            }
            if (st == 2) {
                carry = fmaf(coef, g_incl[(size_t)j * D_ + d], carry);
                break;
            }
            carry = fmaf(coef, g_agg[(size_t)j * D_ + d], carry);
            coef *= Q;
            j -= B_;
        }
    }

    // publish inclusive: s at tile end = last + Q * S_in
    g_incl[(size_t)ticket * D_ + d] = fmaf(Q, carry, last);
    __threadfence();
    __syncthreads();
    if (threadIdx.x == 0) st_release(&g_status[ticket], 2);

    // ---- fixup + coalesced store: s_{t0+i} = l_i + q^{i+1} * S_in ----
    float* op = out + base;
    float c = q;
    #pragma unroll
    for (int i = 0; i < L_; ++i) {
        op[(size_t)i * D_] = fmaf(c, carry, v[i]);
        c *= q;
    }
}

extern "C" void kernel_launch(void* const* d_in, const int* in_sizes, int n_in,
                              void* d_out, int out_size) {
    const float* x     = (const float*)d_in[0];   // (16, 4096, 512) fp32
    const float* alpha = (const float*)d_in[1];   // (1, 1, 512) fp32
    float* out = (float*)d_out;
    (void)in_sizes; (void)n_in; (void)out_size;

    es_clear_kernel<<<(NTILES + 255) / 256, 256>>>();
    es_scan_kernel<<<NTILES, TPB>>>(x, alpha, out);
}

// round 4
// speedup vs baseline: 1.8307x; 1.8307x over previous
#include <cuda_runtime.h>
#include <cuda_bf16.h>
#include <cstdint>

// ExponentialSmoothingLayer: s_0 = x_0; s_t = a*x_t + (1-a)*s_{t-1}, a = sigmoid(alpha[d])
// x: (B=16, T=4096, D=512) fp32 -> out same shape.
//
// Single-pass decoupled-lookback scan, v2:
//  - tile = (b, 32 t, all 512 d); block 512 thr; x tile staged in SMEM via ONE
//    cp.async.bulk (64 KB contiguous) -> low regs -> 3 blocks/SM (was 2)
//  - parallel-window lookback: warp 0 reads 32 predecessor statuses in one
//    coalesced access + ballot; combine loads issued in parallel, truncated
//    when Q^i underflows relevance (Q = (1-a)^32, residual < 1e-12 << 1e-3 tol)

#define B_  16
#define T_  4096
#define D_  512
#define L_  32
#define NTB (T_ / L_)            // 128 tiles per batch row
#define NTILES (B_ * NTB)        // 2048
#define TPB 512
#define TILE_BYTES (L_ * D_ * 4) // 65536

// -------- scratch (static device arrays; no runtime allocation) --------
__device__ float        g_agg [NTILES * D_];   // per-tile local-scan last value
__device__ float        g_incl[NTILES * D_];   // per-tile true inclusive state
__device__ int          g_status[NTILES];      // [b][tb] row-major: 0/1(agg)/2(incl)
__device__ unsigned int g_ticket;

// -------- PTX helpers --------
__device__ __forceinline__ int ld_acquire(const int* p) {
    int v; asm volatile("ld.acquire.gpu.s32 %0, [%1];" : "=r"(v) : "l"(p) : "memory"); return v;
}
__device__ __forceinline__ void st_release(int* p, int v) {
    asm volatile("st.release.gpu.s32 [%0], %1;" :: "l"(p), "r"(v) : "memory");
}
__device__ __forceinline__ unsigned smem_u32(const void* p) {
    unsigned a;
    asm("{ .reg .u64 t; cvta.to.shared.u64 t, %1; cvt.u32.u64 %0, t; }" : "=r"(a) : "l"(p));
    return a;
}

// -------- per-replay flag reset --------
__global__ void es_clear_kernel() {
    int i = blockIdx.x * blockDim.x + threadIdx.x;
    if (i < NTILES) g_status[i] = 0;
    if (i == 0)     g_ticket = 0u;
}

__global__ void __launch_bounds__(TPB, 3)
es_scan_kernel(const float* __restrict__ x,
               const float* __restrict__ alpha,
               float* __restrict__ out) {
    extern __shared__ float tile[];                 // L_ * D_ floats (64 KB)
    __shared__ unsigned long long mbar;
    __shared__ unsigned s_ticket;
    __shared__ int s_w;

    const int tid = threadIdx.x;

    if (tid == 0) {
        s_ticket = atomicAdd(&g_ticket, 1u);
        asm volatile("mbarrier.init.shared.b64 [%0], %1;"
                     :: "r"(smem_u32(&mbar)), "r"(1) : "memory");
    }
    __syncthreads();

    const unsigned ticket = s_ticket;               // execution-start ordered
    const int b  = (int)(ticket & (B_ - 1));        // round-robin rows
    const int tb = (int)(ticket >> 4);
    const int lin = b * NTB + tb;                   // status/value index
    const size_t base = ((size_t)b * T_ + (size_t)tb * L_) * (size_t)D_;

    // one bulk async copy: 64 KB contiguous gmem -> smem
    if (tid == 0) {
        unsigned mb = smem_u32(&mbar);
        asm volatile("mbarrier.arrive.expect_tx.shared.b64 _, [%0], %1;"
                     :: "r"(mb), "r"((unsigned)TILE_BYTES) : "memory");
        asm volatile("cp.async.bulk.shared::cta.global.mbarrier::complete_tx::bytes "
                     "[%0], [%1], %2, [%3];"
                     :: "r"(smem_u32(tile)), "l"(x + base),
                        "r"((unsigned)TILE_BYTES), "r"(mb) : "memory");
    }

    // per-channel coefficients (overlaps TMA)
    const float av = alpha[tid];
    const float a  = 1.0f / (1.0f + __expf(-av));
    const float q  = 1.0f - a;
    float Q = q;                                    // Q = q^32
    #pragma unroll
    for (int i = 0; i < 5; ++i) Q *= Q;

    // wait for the bulk copy
    {
        unsigned mb = smem_u32(&mbar);
        unsigned done;
        asm volatile(
            "{\n\t.reg .pred p;\n\t"
            "mbarrier.try_wait.parity.acquire.cta.shared::cta.b64 p, [%1], 0;\n\t"
            "selp.b32 %0, 1, 0, p;\n\t}"
            : "=r"(done) : "r"(mb) : "memory");
        while (!done) {
            asm volatile(
                "{\n\t.reg .pred p;\n\t"
                "mbarrier.try_wait.parity.acquire.cta.shared::cta.b64 p, [%1], 0, 0x989680;\n\t"
                "selp.b32 %0, 1, 0, p;\n\t}"
                : "=r"(done) : "r"(mb) : "memory");
        }
    }

    // pass 1: local scan (zero incoming state), write local values back to smem
    float s = 0.0f, x0;
    #pragma unroll
    for (int t = 0; t < L_; ++t) {
        float v = tile[t * D_ + tid];
        if (t == 0) x0 = v;
        s = fmaf(q, s, a * v);
        tile[t * D_ + tid] = s;
    }
    const float last = s;

    // ---- resolve incoming state carry = inclusive of predecessor tile ----
    float carry;
    if (tb == 0) {
        carry = x0;                                 // s_0 = x_0  <=>  S_in = x_0
    } else {
        // publish aggregate first (forward progress for successors)
        g_agg[(size_t)lin * D_ + tid] = last;
        __threadfence();
        __syncthreads();
        if (tid == 0) st_release(&g_status[lin], 1);

        // parallel-window lookback: warp 0 scans 32 statuses at once
        if (tid < 32) {
            const int idx = tb - 1 - tid;           // this lane's predecessor
            const int* sp = &g_status[b * NTB + idx];
            for (;;) {
                int st = (idx >= 0) ? ld_acquire(sp) : 0;
                unsigned m2 = __ballot_sync(0xffffffffu, st == 2);
                unsigned m0 = __ballot_sync(0xffffffffu, st == 0);
                if (m2) {
                    int i2 = __ffs(m2) - 1;         // nearest INCLUSIVE
                    if ((m0 & ((1u << i2) - 1u)) == 0u) {  // all nearer have agg
                        if (tid == 0) s_w = i2;
                        break;
                    }
                }
                __nanosleep(100);
            }
        }
        __syncthreads();
        const int i2 = s_w;

        // carry = sum_{i<i2} Q^i * agg[tb-1-i]  +  Q^i2 * incl[tb-1-i2]
        // truncate negligible terms: Q^i < 1e-12 contributes < 1e-12 (tol 1e-3)
        const size_t pbase = (size_t)(b * NTB + tb - 1) * D_ + tid;
        carry = 0.0f;
        float coef = 1.0f;
        for (int i = 0; i < i2; ++i) {
            if (coef > 1e-12f)
                carry = fmaf(coef, g_agg[pbase - (size_t)i * D_], carry);
            coef *= Q;
        }
        if (coef > 1e-12f || i2 == 0)
            carry = fmaf(coef, g_incl[pbase - (size_t)i2 * D_], carry);
    }

    // publish inclusive: state at tile end = last + Q * S_in
    g_incl[(size_t)lin * D_ + tid] = fmaf(Q, carry, last);
    __threadfence();
    __syncthreads();
    if (tid == 0) st_release(&g_status[lin], 2);

    // pass 2: fixup + coalesced store: s_{t0+t} = local_t + q^{t+1} * S_in
    float* op = out + base + tid;
    float c = q;
    #pragma unroll
    for (int t = 0; t < L_; ++t) {
        op[(size_t)t * D_] = fmaf(c, carry, tile[t * D_ + tid]);
        c *= q;
    }
}

extern "C" void kernel_launch(void* const* d_in, const int* in_sizes, int n_in,
                              void* d_out, int out_size) {
    const float* x     = (const float*)d_in[0];   // (16, 4096, 512) fp32
    const float* alpha = (const float*)d_in[1];   // (1, 1, 512) fp32
    float* out = (float*)d_out;
    (void)in_sizes; (void)n_in; (void)out_size;

    static bool attr_set = false;
    if (!attr_set) {
        cudaFuncSetAttribute(es_scan_kernel,
                             cudaFuncAttributeMaxDynamicSharedMemorySize,
                             TILE_BYTES);
        attr_set = true;
    }

    es_clear_kernel<<<(NTILES + 255) / 256, 256>>>();
    es_scan_kernel<<<NTILES, TPB, TILE_BYTES>>>(x, alpha, out);
}